// round 2
// baseline (speedup 1.0000x reference)
#include <cuda_runtime.h>
#include <cstdint>

#define NN   15279
#define EE   488928
#define KIN  1024
#define NH   512
#define NC   16

// ---------------- scratch (static device memory; no allocations) ----------------
__device__ float g_Z1[ (size_t)NN * NH  ];   // fused-embed H @ W1       31.3 MB
__device__ float g_H1[ (size_t)NN * NH  ];   // relu(spmm(Z1)+b1)        31.3 MB
__device__ float g_Z2[ (size_t)NN * NC  ];   // H1 @ W2                   1.0 MB
__device__ int   g_x32[NN * 8];              // x normalized to int32
__device__ int   g_cnt   [NN];
__device__ int   g_rowptr[NN + 1];
__device__ int   g_cursor[NN];
__device__ int   g_colS[EE];
__device__ float g_valS[EE];
__device__ int   g_xIs64;

// ---------------- dtype detection for x (int64 vs int32) ----------------
// If x is int64 (values < 2^31), every odd 32-bit word is 0. If int32, the odd
// words are random indices in [0,10000) -> P(all 64 zero) ~ 1e-256.
__global__ void k_detect(const int* __restrict__ xr) {
    if (threadIdx.x == 0) {
        int f = 1;
        for (int l = 0; l < 64; ++l) {
            if (xr[2 * l + 1] != 0) { f = 0; break; }
        }
        g_xIs64 = f;
    }
}

// normalize x to flat int32 (works for either input dtype)
__global__ void k_xcast(const int* __restrict__ xr) {
    int i = blockIdx.x * 256 + threadIdx.x;
    if (i < NN * 8) {
        g_x32[i] = g_xIs64 ? xr[2 * i] : xr[i];   // little-endian low word
    }
}

// ---------------- packed fp32x2 helpers (Blackwell FFMA2 path) ----------------
__device__ __forceinline__ unsigned long long pk2(float lo, float hi) {
    unsigned long long r;
    asm("mov.b64 %0, {%1, %2};" : "=l"(r) : "f"(lo), "f"(hi));
    return r;
}
__device__ __forceinline__ void fma2(unsigned long long& d,
                                     unsigned long long a, unsigned long long b) {
    asm("fma.rn.f32x2 %0, %1, %2, %0;" : "+l"(d) : "l"(a), "l"(b));
}
__device__ __forceinline__ void up2(unsigned long long v, float& lo, float& hi) {
    asm("mov.b64 {%0, %1}, %2;" : "=f"(lo), "=f"(hi) : "l"(v));
}

// fused A-operand fetch: A[row, k] = relu(emb[x[row, k>>7]][k&127])
__device__ __forceinline__ float4 ldEmb(const float* __restrict__ emb, int tok, int d) {
    float4 z = {0.f, 0.f, 0.f, 0.f};
    if (tok < 0) return z;
    float4 v = *(const float4*)(emb + (size_t)tok * 128 + d);
    v.x = fmaxf(v.x, 0.0f); v.y = fmaxf(v.y, 0.0f);
    v.z = fmaxf(v.z, 0.0f); v.w = fmaxf(v.w, 0.0f);
    return v;
}

// ---------------- GEMM1 (fused embed+relu): Z1 = relu(emb[x]) @ W1 ----------------
// 128x128 block tile, BK=16, double-buffered smem, 8x8 per-thread microtile
// held as 32 f32x2 accumulators (FFMA2). A tiles are gathered straight from the
// L2-resident embedding table; tokens for this thread's 2 rows cached in regs.
__global__ __launch_bounds__(256, 2) void k_gemm1(const float* __restrict__ W,
                                                  const float* __restrict__ emb) {
    __shared__ float As[2][16][132];   // [k][m], padded row
    __shared__ float Bs[2][16][128];   // [k][n]

    const int tid     = threadIdx.x;
    const int rowBase = blockIdx.y * 128;
    const int colBase = blockIdx.x * 128;

    const int mrow = tid >> 2;           // 0..63 (and +64)
    const int ka   = (tid & 3) * 4;      // k quad within BK
    const int kb   = tid >> 5;           // 0..7 (and +8)
    const int nb   = (tid & 31) * 4;     // 0..124

    // cache this thread's token indices (2 rows x 8 slots)
    const int r0 = rowBase + mrow;
    const int r1 = r0 + 64;
    int tok0[8], tok1[8];
#pragma unroll
    for (int s = 0; s < 8; ++s) {
        tok0[s] = (r0 < NN) ? g_x32[r0 * 8 + s] : -1;
        tok1[s] = (r1 < NN) ? g_x32[r1 * 8 + s] : -1;
    }

    // --- prologue: load tile 0 (k = ka < 16 -> slot 0, d = ka) ---
    float4 a0 = ldEmb(emb, tok0[0], ka);
    float4 a1 = ldEmb(emb, tok1[0], ka);
    float4 b0 = *(const float4*)(W + (size_t)(kb)     * NH + colBase + nb);
    float4 b1 = *(const float4*)(W + (size_t)(kb + 8) * NH + colBase + nb);
    {
        const float* pa0 = (const float*)&a0;
        const float* pa1 = (const float*)&a1;
#pragma unroll
        for (int i = 0; i < 4; ++i) {
            As[0][ka + i][mrow]      = pa0[i];
            As[0][ka + i][mrow + 64] = pa1[i];
        }
        *(float4*)&Bs[0][kb][nb]     = b0;
        *(float4*)&Bs[0][kb + 8][nb] = b1;
    }
    __syncthreads();

    unsigned long long acc[8][4];
#pragma unroll
    for (int m = 0; m < 8; ++m)
#pragma unroll
        for (int n = 0; n < 4; ++n) acc[m][n] = 0ULL;

    const int tx = tid & 15;   // n dim
    const int ty = tid >> 4;   // m dim

    for (int t = 0; t < 64; ++t) {
        const int buf = t & 1;
        if (t < 63) {
            const int k    = (t + 1) * 16 + ka;
            const int slot = k >> 7;
            const int d    = k & 127;
            a0 = ldEmb(emb, tok0[slot], d);
            a1 = ldEmb(emb, tok1[slot], d);
            const int kt = (t + 1) * 16;
            b0 = *(const float4*)(W + (size_t)(kt + kb)     * NH + colBase + nb);
            b1 = *(const float4*)(W + (size_t)(kt + kb + 8) * NH + colBase + nb);
        }
#pragma unroll
        for (int kk = 0; kk < 16; ++kk) {
            float4 x0 = *(const float4*)&As[buf][kk][ty * 8];
            float4 x1 = *(const float4*)&As[buf][kk][ty * 8 + 4];
            float4 y0 = *(const float4*)&Bs[buf][kk][tx * 8];
            float4 y1 = *(const float4*)&Bs[buf][kk][tx * 8 + 4];
            unsigned long long bp0 = pk2(y0.x, y0.y);
            unsigned long long bp1 = pk2(y0.z, y0.w);
            unsigned long long bp2 = pk2(y1.x, y1.y);
            unsigned long long bp3 = pk2(y1.z, y1.w);
            float am[8] = {x0.x, x0.y, x0.z, x0.w, x1.x, x1.y, x1.z, x1.w};
#pragma unroll
            for (int m = 0; m < 8; ++m) {
                unsigned long long ad = pk2(am[m], am[m]);
                fma2(acc[m][0], ad, bp0);
                fma2(acc[m][1], ad, bp1);
                fma2(acc[m][2], ad, bp2);
                fma2(acc[m][3], ad, bp3);
            }
        }
        if (t < 63) {
            const int nbuf = buf ^ 1;
            const float* pa0 = (const float*)&a0;
            const float* pa1 = (const float*)&a1;
#pragma unroll
            for (int i = 0; i < 4; ++i) {
                As[nbuf][ka + i][mrow]      = pa0[i];
                As[nbuf][ka + i][mrow + 64] = pa1[i];
            }
            *(float4*)&Bs[nbuf][kb][nb]     = b0;
            *(float4*)&Bs[nbuf][kb + 8][nb] = b1;
        }
        __syncthreads();
    }

    // --- epilogue: store 8x8 ---
#pragma unroll
    for (int m = 0; m < 8; ++m) {
        const int row = rowBase + ty * 8 + m;
        if (row < NN) {
            float4 o0, o1;
            up2(acc[m][0], o0.x, o0.y);
            up2(acc[m][1], o0.z, o0.w);
            up2(acc[m][2], o1.x, o1.y);
            up2(acc[m][3], o1.z, o1.w);
            float* out = g_Z1 + (size_t)row * NH + colBase + tx * 8;
            *(float4*)(out)     = o0;
            *(float4*)(out + 4) = o1;
        }
    }
}

// ---------------- CSR build ----------------
__global__ void k_zero() {
    int i = blockIdx.x * 256 + threadIdx.x;
    if (i < NN) g_cnt[i] = 0;
}

__global__ void k_hist(const int* __restrict__ rows) {
    int e = blockIdx.x * 256 + threadIdx.x;
    if (e < EE) atomicAdd(&g_cnt[rows[e]], 1);
}

// single-block scan over NN counters (1024 threads x 15 elements)
__global__ void k_scan() {
    __shared__ int ssum[1024];
    const int tid  = threadIdx.x;
    const int CH   = 15;                 // 1024*15 = 15360 >= NN
    const int base = tid * CH;
    int loc[CH];
    int run = 0;
#pragma unroll
    for (int i = 0; i < CH; ++i) {
        int idx = base + i;
        int v = (idx < NN) ? g_cnt[idx] : 0;
        loc[i] = run;
        run += v;
    }
    ssum[tid] = run;
    __syncthreads();
    for (int d = 1; d < 1024; d <<= 1) {
        int v = (tid >= d) ? ssum[tid - d] : 0;
        __syncthreads();
        ssum[tid] += v;
        __syncthreads();
    }
    int off = ssum[tid] - run;           // exclusive offset of this chunk
#pragma unroll
    for (int i = 0; i < CH; ++i) {
        int idx = base + i;
        if (idx < NN) {
            int p = off + loc[i];
            g_rowptr[idx] = p;
            g_cursor[idx] = p;
        }
    }
    if (tid == 1023) g_rowptr[NN] = ssum[1023];
}

__global__ void k_scatter(const int* __restrict__ rows, const int* __restrict__ cols,
                          const float* __restrict__ vals) {
    int e = blockIdx.x * 256 + threadIdx.x;
    if (e < EE) {
        int r = rows[e];
        int p = atomicAdd(&g_cursor[r], 1);
        g_colS[p] = cols[e];
        g_valS[p] = vals[e];
    }
}

// ---------------- SPMM1: H1 = relu(adj @ Z1 + b1) ----------------
// one block (128 threads) per row; thread t owns features [4t, 4t+4)
__global__ void k_spmm1(const float* __restrict__ b1) {
    __shared__ int   sc[128];
    __shared__ float sv[128];
    const int row = blockIdx.x;
    const int tid = threadIdx.x;
    const int s = g_rowptr[row];
    const int e = g_rowptr[row + 1];
    float4 acc = {0.f, 0.f, 0.f, 0.f};
    for (int base = s; base < e; base += 128) {
        int i = base + tid;
        if (i < e) { sc[tid] = g_colS[i]; sv[tid] = g_valS[i]; }
        __syncthreads();
        int m = e - base; if (m > 128) m = 128;
        for (int j = 0; j < m; ++j) {
            float v = sv[j];
            int   c = sc[j];
            float4 z = *(const float4*)(g_Z1 + (size_t)c * NH + tid * 4);
            acc.x += v * z.x; acc.y += v * z.y;
            acc.z += v * z.z; acc.w += v * z.w;
        }
        __syncthreads();
    }
    float4 bb = *(const float4*)(b1 + tid * 4);
    float4 o;
    o.x = fmaxf(acc.x + bb.x, 0.0f);
    o.y = fmaxf(acc.y + bb.y, 0.0f);
    o.z = fmaxf(acc.z + bb.z, 0.0f);
    o.w = fmaxf(acc.w + bb.w, 0.0f);
    *(float4*)(g_H1 + (size_t)row * NH + tid * 4) = o;
}

// ---------------- GEMM2: Z2 = H1[NN x 512] @ W2[512 x 16] ----------------
// 8 warps per block, one row per warp; W2 transposed in smem.
__global__ void k_gemm2(const float* __restrict__ W2) {
    __shared__ float Ws[16 * 513];      // Ws[c*513 + k]
    const int tid = threadIdx.x;
    for (int idx = tid; idx < NH * NC; idx += 256) {
        int k = idx >> 4, c = idx & 15;
        Ws[c * 513 + k] = W2[idx];
    }
    __syncthreads();
    const int w    = tid >> 5;
    const int lane = tid & 31;
    const int row  = blockIdx.x * 8 + w;
    if (row >= NN) return;
    float acc[16];
#pragma unroll
    for (int c = 0; c < 16; ++c) acc[c] = 0.0f;
    const float* hr = g_H1 + (size_t)row * NH;
    for (int k = lane; k < NH; k += 32) {
        float h = hr[k];
#pragma unroll
        for (int c = 0; c < 16; ++c) acc[c] += h * Ws[c * 513 + k];
    }
#pragma unroll
    for (int c = 0; c < 16; ++c)
        for (int o = 16; o; o >>= 1)
            acc[c] += __shfl_xor_sync(0xffffffffu, acc[c], o);
    if (lane == 0) {
#pragma unroll
        for (int c = 0; c < 16; ++c) g_Z2[(size_t)row * NC + c] = acc[c];
    }
}

// ---------------- SPMM2: out = adj @ Z2 + b2 ----------------
__global__ void k_spmm2(const float* __restrict__ b2, float* __restrict__ out) {
    const int w    = threadIdx.x >> 5;
    const int lane = threadIdx.x & 31;
    const int row  = blockIdx.x * 8 + w;
    if (row >= NN) return;
    const int s = g_rowptr[row];
    const int e = g_rowptr[row + 1];
    float acc = 0.0f;
    for (int i = s; i < e; ++i) {
        int   c = g_colS[i];     // warp-broadcast
        float v = g_valS[i];
        if (lane < 16) acc += v * g_Z2[(size_t)c * NC + lane];
    }
    if (lane < 16) out[(size_t)row * NC + lane] = acc + b2[lane];
}

// ---------------- launch ----------------
extern "C" void kernel_launch(void* const* d_in, const int* in_sizes, int n_in,
                              void* d_out, int out_size) {
    (void)in_sizes; (void)n_in; (void)out_size;
    const int*   x    = (const int*)  d_in[0];
    const int*   rows = (const int*)  d_in[1];
    const int*   cols = (const int*)  d_in[2];
    const float* vals = (const float*)d_in[3];
    const float* emb  = (const float*)d_in[4];
    const float* W1   = (const float*)d_in[5];
    const float* b1   = (const float*)d_in[6];
    const float* W2   = (const float*)d_in[7];
    const float* b2   = (const float*)d_in[8];
    float* out = (float*)d_out;

    k_detect<<<1, 32>>>(x);
    k_xcast<<<(NN * 8 + 255) / 256, 256>>>(x);

    // CSR build
    k_zero<<<(NN + 255) / 256, 256>>>();
    k_hist<<<(EE + 255) / 256, 256>>>(rows);
    k_scan<<<1, 1024>>>();
    k_scatter<<<(EE + 255) / 256, 256>>>(rows, cols, vals);

    dim3 g1(4, 120);
    k_gemm1<<<g1, 256>>>(W1, emb);

    k_spmm1<<<NN, 128>>>(b1);
    k_gemm2<<<(NN + 7) / 8, 256>>>(W2);
    k_spmm2<<<(NN + 7) / 8, 256>>>(b2, out);
}

// round 16
// speedup vs baseline: 1.4442x; 1.4442x over previous
#include <cuda_runtime.h>
#include <cuda_bf16.h>
#include <cstdint>

#define NN   15279
#define EE   488928
#define KIN  1024
#define NH   512
#define NC   16

// ---------------- scratch (static device memory; no allocations) ----------------
__device__ float g_Z1[ (size_t)NN * NH  ];   // fused-embed H @ W1       31.3 MB
__device__ float g_H1[ (size_t)NN * NH  ];   // relu(spmm(Z1)+b1)        31.3 MB
__device__ float g_Z2[ (size_t)NN * NC  ];   // H1 @ W2                   1.0 MB
__device__ int   g_x32[NN * 8];              // x normalized to int32
__device__ int   g_cnt   [NN];
__device__ int   g_rowptr[NN + 1];
__device__ int   g_cursor[NN];
__device__ int   g_colS[EE];
__device__ float g_valS[EE];
__device__ int   g_xIs64;
// bf16 hi/lo images of W1, tiled for the mma kernel:
// [colBlk 0..3][iter 0..31] tiles of [128 n][32 k] bf16 (8 KB each) = 1 MB each
__device__ uint4 g_Bhi[4 * 32 * 512];
__device__ uint4 g_Blo[4 * 32 * 512];

__device__ __forceinline__ uint32_t smem_u32(const void* p) {
    uint32_t a;
    asm("{ .reg .u64 t; cvta.to.shared.u64 t, %1; cvt.u32.u64 %0, t; }" : "=r"(a) : "l"(p));
    return a;
}
__device__ __forceinline__ uint32_t pack_bf2(float a, float b) {
    __nv_bfloat162 t = __floats2bfloat162_rn(a, b);
    return *(uint32_t*)&t;
}

// warp-level bf16 mma (sm_80+ plain target; runs on HMMA fallback path on sm_103)
#define MMA_BF16(C, A, B0, B1) \
    asm volatile("mma.sync.aligned.m16n8k16.row.col.f32.bf16.bf16.f32 " \
        "{%0,%1,%2,%3}, {%4,%5,%6,%7}, {%8,%9}, {%0,%1,%2,%3};" \
        : "+f"((C)[0]), "+f"((C)[1]), "+f"((C)[2]), "+f"((C)[3]) \
        : "r"((A)[0]), "r"((A)[1]), "r"((A)[2]), "r"((A)[3]), "r"(B0), "r"(B1))

#define LDSM4(R, ADDR) \
    asm volatile("ldmatrix.sync.aligned.m8n8.x4.shared.b16 {%0,%1,%2,%3}, [%4];" \
        : "=r"((R)[0]), "=r"((R)[1]), "=r"((R)[2]), "=r"((R)[3]) : "r"(ADDR))

// ---------------- dtype detection for x (int64 vs int32) ----------------
__global__ void k_detect(const int* __restrict__ xr) {
    if (threadIdx.x == 0) {
        int f = 1;
        for (int l = 0; l < 64; ++l) {
            if (xr[2 * l + 1] != 0) { f = 0; break; }
        }
        g_xIs64 = f;
    }
}

__global__ void k_xcast(const int* __restrict__ xr) {
    int i = blockIdx.x * 256 + threadIdx.x;
    if (i < NN * 8) {
        g_x32[i] = g_xIs64 ? xr[2 * i] : xr[i];
    }
}

// ---------------- W1 -> bf16 hi/lo tile images ----------------
// tile (colBlk, iter): [128 n][32 k] bf16, n-major rows of 64 B, 8 KB per tile
__global__ void k_prepB(const float* __restrict__ W1) {
    int t = blockIdx.x * 256 + threadIdx.x;          // 262144 = 512 n * 512 k-pairs
    if (t >= 512 * 512) return;
    int n  = t & 511;
    int k  = (t >> 9) * 2;
    float v0 = W1[(size_t)k * NH + n];
    float v1 = W1[(size_t)(k + 1) * NH + n];
    __nv_bfloat162 hv = __floats2bfloat162_rn(v0, v1);
    uint32_t hw = *(uint32_t*)&hv;
    uint32_t lw = pack_bf2(v0 - __bfloat162float(hv.x), v1 - __bfloat162float(hv.y));
    int colBlk = n >> 7, nn = n & 127, it = k >> 5, kk = k & 31;
    uint32_t byte = (((uint32_t)(colBlk * 32 + it) * 128u + (uint32_t)nn) * 64u)
                  + (uint32_t)kk * 2u;
    *(uint32_t*)((char*)g_Bhi + byte) = hw;
    *(uint32_t*)((char*)g_Blo + byte) = lw;
}

// ---------------- GEMM1 via mma.sync: Z1 = relu(emb[x]) @ W1 ----------------
// CTA 128x128, BK=32, split-bf16 (3 products), double-buffered smem.
// smem stage (40960 B): Ahi[128x80B] | Alo | Bhi[128x80B] | Blo  (rows padded 64->80B)
#define STG   40960
#define G1_SMEM (2 * STG)
__global__ __launch_bounds__(256, 1) void k_gemm1m(const float* __restrict__ emb) {
    extern __shared__ char sm[];
    const uint32_t smBase = smem_u32(sm);
    const int tid  = threadIdx.x;
    const int lane = tid & 31;
    const int wid  = tid >> 5;
    const int colBlk  = blockIdx.x;        // 0..3
    const int rowBase = blockIdx.y * 128;  // 120 blocks

    // A loader identity: 2 threads per row, 16 k each
    const int ar = tid >> 1;
    const int h  = tid & 1;
    const int arow = rowBase + ar;
    const int trow = (arow < NN) ? arow : 0;
    int tok[8];
#pragma unroll
    for (int s = 0; s < 8; ++s) tok[s] = g_x32[trow * 8 + s];

    // warp tiling: 4 warps in M (32 rows each), 2 in N (64 cols each)
    const int wm = (wid & 3) * 32;
    const int wn = (wid >> 2) * 64;

    float c[2][8][4];
#pragma unroll
    for (int mt = 0; mt < 2; ++mt)
#pragma unroll
        for (int nt = 0; nt < 8; ++nt)
#pragma unroll
            for (int q = 0; q < 4; ++q) c[mt][nt][q] = 0.0f;

    uint32_t aH[8], aL[8];
    uint4 bH[2], bL[2];

    auto ldGlobal = [&](int it) {
        const int slot = it >> 2;
        const int off  = (it & 3) * 32 + h * 16;
        const float* src = emb + (size_t)tok[slot] * 128 + off;
#pragma unroll
        for (int q = 0; q < 4; ++q) {
            float4 v = ((const float4*)src)[q];
            float f0 = fmaxf(v.x, 0.f), f1 = fmaxf(v.y, 0.f);
            float f2 = fmaxf(v.z, 0.f), f3 = fmaxf(v.w, 0.f);
            __nv_bfloat162 h0 = __floats2bfloat162_rn(f0, f1);
            __nv_bfloat162 h1 = __floats2bfloat162_rn(f2, f3);
            aH[q * 2]     = *(uint32_t*)&h0;
            aH[q * 2 + 1] = *(uint32_t*)&h1;
            aL[q * 2]     = pack_bf2(f0 - __bfloat162float(h0.x), f1 - __bfloat162float(h0.y));
            aL[q * 2 + 1] = pack_bf2(f2 - __bfloat162float(h1.x), f3 - __bfloat162float(h1.y));
        }
        const uint4* sh = g_Bhi + (size_t)(colBlk * 32 + it) * 512;
        const uint4* sl = g_Blo + (size_t)(colBlk * 32 + it) * 512;
        bH[0] = sh[tid]; bH[1] = sh[tid + 256];
        bL[0] = sl[tid]; bL[1] = sl[tid + 256];
    };

    auto stStage = [&](int s) {
        char* base = sm + s * STG;
        char* a = base + ar * 80 + h * 32;
        *(uint4*)(a)              = *(uint4*)(aH);
        *(uint4*)(a + 16)         = *(uint4*)(aH + 4);
        *(uint4*)(a + 10240)      = *(uint4*)(aL);
        *(uint4*)(a + 10240 + 16) = *(uint4*)(aL + 4);
#pragma unroll
        for (int j = 0; j < 2; ++j) {
            int u = tid + j * 256;           // 0..511: row = u/4, 16B-chunk q = u%4
            int row = u >> 2, q = u & 3;
            *(uint4*)(base + 20480 + row * 80 + q * 16) = bH[j];
            *(uint4*)(base + 30720 + row * 80 + q * 16) = bL[j];
        }
    };

    auto compute = [&](int s) {
        const uint32_t base = smBase + s * STG;
        const int rl = (lane & 7) + ((lane >> 3) & 1) * 8;   // ldmatrix row-in-16
        const int kh = (lane >> 4) * 8;                       // k half select
#pragma unroll
        for (int ks = 0; ks < 2; ++ks) {
            const int kcb = (ks * 16 + kh) * 2;               // byte offset in row
            uint32_t ah[2][4], al[2][4];
#pragma unroll
            for (int mt = 0; mt < 2; ++mt) {
                uint32_t addr = base + (uint32_t)(wm + mt * 16 + rl) * 80u + kcb;
                LDSM4(ah[mt], addr);
                LDSM4(al[mt], addr + 10240);
            }
#pragma unroll
            for (int ntp = 0; ntp < 4; ++ntp) {
                uint32_t rb = base + 20480 + (uint32_t)(wn + ntp * 16 + rl) * 80u + kcb;
                uint32_t bh[4], bl[4];
                LDSM4(bh, rb);
                LDSM4(bl, rb + 10240);
#pragma unroll
                for (int mt = 0; mt < 2; ++mt) {
                    MMA_BF16(c[mt][2 * ntp],     ah[mt], bh[0], bh[2]);
                    MMA_BF16(c[mt][2 * ntp],     ah[mt], bl[0], bl[2]);
                    MMA_BF16(c[mt][2 * ntp],     al[mt], bh[0], bh[2]);
                    MMA_BF16(c[mt][2 * ntp + 1], ah[mt], bh[1], bh[3]);
                    MMA_BF16(c[mt][2 * ntp + 1], ah[mt], bl[1], bl[3]);
                    MMA_BF16(c[mt][2 * ntp + 1], al[mt], bh[1], bh[3]);
                }
            }
        }
    };

    // ---- mainloop: 32 iterations of BK=32, double-buffered ----
    ldGlobal(0);
    stStage(0);
    __syncthreads();
#pragma unroll 1
    for (int it = 0; it < 32; ++it) {
        const int s = it & 1;
        if (it + 1 < 32) ldGlobal(it + 1);
        compute(s);
        if (it + 1 < 32) stStage(s ^ 1);
        __syncthreads();
    }

    // ---- epilogue ----
    const int group = lane >> 2;
    const int tig   = lane & 3;
#pragma unroll
    for (int mt = 0; mt < 2; ++mt) {
#pragma unroll
        for (int nt = 0; nt < 8; ++nt) {
            int r0 = rowBase + wm + mt * 16 + group;
            int cc = colBlk * 128 + wn + nt * 8 + tig * 2;
            if (r0 < NN) {
                float2 v = { c[mt][nt][0], c[mt][nt][1] };
                *(float2*)(g_Z1 + (size_t)r0 * NH + cc) = v;
            }
            int r1 = r0 + 8;
            if (r1 < NN) {
                float2 v = { c[mt][nt][2], c[mt][nt][3] };
                *(float2*)(g_Z1 + (size_t)r1 * NH + cc) = v;
            }
        }
    }
}

// ---------------- CSR build ----------------
__global__ void k_zero() {
    int i = blockIdx.x * 256 + threadIdx.x;
    if (i < NN) g_cnt[i] = 0;
}

__global__ void k_hist(const int* __restrict__ rows) {
    int e = blockIdx.x * 256 + threadIdx.x;
    if (e < EE) atomicAdd(&g_cnt[rows[e]], 1);
}

__global__ void k_scan() {
    __shared__ int ssum[1024];
    const int tid  = threadIdx.x;
    const int CH   = 15;
    const int base = tid * CH;
    int loc[CH];
    int run = 0;
#pragma unroll
    for (int i = 0; i < CH; ++i) {
        int idx = base + i;
        int v = (idx < NN) ? g_cnt[idx] : 0;
        loc[i] = run;
        run += v;
    }
    ssum[tid] = run;
    __syncthreads();
    for (int d = 1; d < 1024; d <<= 1) {
        int v = (tid >= d) ? ssum[tid - d] : 0;
        __syncthreads();
        ssum[tid] += v;
        __syncthreads();
    }
    int off = ssum[tid] - run;
#pragma unroll
    for (int i = 0; i < CH; ++i) {
        int idx = base + i;
        if (idx < NN) {
            int p = off + loc[i];
            g_rowptr[idx] = p;
            g_cursor[idx] = p;
        }
    }
    if (tid == 1023) g_rowptr[NN] = ssum[1023];
}

__global__ void k_scatter(const int* __restrict__ rows, const int* __restrict__ cols,
                          const float* __restrict__ vals) {
    int e = blockIdx.x * 256 + threadIdx.x;
    if (e < EE) {
        int r = rows[e];
        int p = atomicAdd(&g_cursor[r], 1);
        g_colS[p] = cols[e];
        g_valS[p] = vals[e];
    }
}

// ---------------- SPMM1: H1 = relu(adj @ Z1 + b1) ----------------
__global__ void k_spmm1(const float* __restrict__ b1) {
    __shared__ int   sc[128];
    __shared__ float sv[128];
    const int row = blockIdx.x;
    const int tid = threadIdx.x;
    const int s = g_rowptr[row];
    const int e = g_rowptr[row + 1];
    float4 acc = {0.f, 0.f, 0.f, 0.f};
    for (int base = s; base < e; base += 128) {
        int i = base + tid;
        if (i < e) { sc[tid] = g_colS[i]; sv[tid] = g_valS[i]; }
        __syncthreads();
        int m = e - base; if (m > 128) m = 128;
        for (int j = 0; j < m; ++j) {
            float v = sv[j];
            int   c = sc[j];
            float4 z = *(const float4*)(g_Z1 + (size_t)c * NH + tid * 4);
            acc.x += v * z.x; acc.y += v * z.y;
            acc.z += v * z.z; acc.w += v * z.w;
        }
        __syncthreads();
    }
    float4 bb = *(const float4*)(b1 + tid * 4);
    float4 o;
    o.x = fmaxf(acc.x + bb.x, 0.0f);
    o.y = fmaxf(acc.y + bb.y, 0.0f);
    o.z = fmaxf(acc.z + bb.z, 0.0f);
    o.w = fmaxf(acc.w + bb.w, 0.0f);
    *(float4*)(g_H1 + (size_t)row * NH + tid * 4) = o;
}

// ---------------- GEMM2: Z2 = H1[NN x 512] @ W2[512 x 16] ----------------
__global__ void k_gemm2(const float* __restrict__ W2) {
    __shared__ float Ws[16 * 513];
    const int tid = threadIdx.x;
    for (int idx = tid; idx < NH * NC; idx += 256) {
        int k = idx >> 4, c = idx & 15;
        Ws[c * 513 + k] = W2[idx];
    }
    __syncthreads();
    const int w    = tid >> 5;
    const int lane = tid & 31;
    const int row  = blockIdx.x * 8 + w;
    if (row >= NN) return;
    float acc[16];
#pragma unroll
    for (int c = 0; c < 16; ++c) acc[c] = 0.0f;
    const float* hr = g_H1 + (size_t)row * NH;
    for (int k = lane; k < NH; k += 32) {
        float h = hr[k];
#pragma unroll
        for (int c = 0; c < 16; ++c) acc[c] += h * Ws[c * 513 + k];
    }
#pragma unroll
    for (int c = 0; c < 16; ++c)
        for (int o = 16; o; o >>= 1)
            acc[c] += __shfl_xor_sync(0xffffffffu, acc[c], o);
    if (lane == 0) {
#pragma unroll
        for (int c = 0; c < 16; ++c) g_Z2[(size_t)row * NC + c] = acc[c];
    }
}

// ---------------- SPMM2: out = adj @ Z2 + b2 ----------------
__global__ void k_spmm2(const float* __restrict__ b2, float* __restrict__ out) {
    const int w    = threadIdx.x >> 5;
    const int lane = threadIdx.x & 31;
    const int row  = blockIdx.x * 8 + w;
    if (row >= NN) return;
    const int s = g_rowptr[row];
    const int e = g_rowptr[row + 1];
    float acc = 0.0f;
    for (int i = s; i < e; ++i) {
        int   c = g_colS[i];
        float v = g_valS[i];
        if (lane < 16) acc += v * g_Z2[(size_t)c * NC + lane];
    }
    if (lane < 16) out[(size_t)row * NC + lane] = acc + b2[lane];
}

// ---------------- launch ----------------
extern "C" void kernel_launch(void* const* d_in, const int* in_sizes, int n_in,
                              void* d_out, int out_size) {
    (void)in_sizes; (void)n_in; (void)out_size;
    const int*   x    = (const int*)  d_in[0];
    const int*   rows = (const int*)  d_in[1];
    const int*   cols = (const int*)  d_in[2];
    const float* vals = (const float*)d_in[3];
    const float* emb  = (const float*)d_in[4];
    const float* W1   = (const float*)d_in[5];
    const float* b1   = (const float*)d_in[6];
    const float* W2   = (const float*)d_in[7];
    const float* b2   = (const float*)d_in[8];
    float* out = (float*)d_out;

    cudaFuncSetAttribute(k_gemm1m, cudaFuncAttributeMaxDynamicSharedMemorySize, G1_SMEM);

    k_detect<<<1, 32>>>(x);
    k_xcast<<<(NN * 8 + 255) / 256, 256>>>(x);
    k_prepB<<<1024, 256>>>(W1);

    // CSR build
    k_zero<<<(NN + 255) / 256, 256>>>();
    k_hist<<<(EE + 255) / 256, 256>>>(rows);
    k_scan<<<1, 1024>>>();
    k_scatter<<<(EE + 255) / 256, 256>>>(rows, cols, vals);

    dim3 g1(4, 120);
    k_gemm1m<<<g1, 256, G1_SMEM>>>(emb);

    k_spmm1<<<NN, 128>>>(b1);
    k_gemm2<<<(NN + 7) / 8, 256>>>(W2);
    k_spmm2<<<(NN + 7) / 8, 256>>>(b2, out);
}